// round 11
// baseline (speedup 1.0000x reference)
#include <cuda_runtime.h>
#include <cuda_bf16.h>
#include <math.h>
#include <stdint.h>

#define N_SRC   10000
#define N_DST   10000
#define N_TOT   20000
#define IN_SRC  512
#define IN_DST  256
#define HID     512
#define OUTD    256
#define N_EDGES 160000
#define EPS     1e-5f
#define MREG    10000
#define YTILES  79

// ---------------- device scratch ----------------
__device__ __align__(16) __nv_bfloat16 g_AH[(size_t)N_TOT * HID];
__device__ __align__(16) __nv_bfloat16 g_AL[(size_t)N_TOT * HID];
__device__ __align__(16) __nv_bfloat16 g_X1H[(size_t)N_TOT * HID];
__device__ __align__(16) __nv_bfloat16 g_X1L[(size_t)N_TOT * HID];
__device__ __align__(16) __nv_bfloat16 g_MH[(size_t)N_DST * HID];
__device__ __align__(16) __nv_bfloat16 g_ML[(size_t)N_DST * HID];
__device__ __align__(16) __nv_bfloat16 g_XSH[(size_t)N_SRC * IN_SRC], g_XSL[(size_t)N_SRC * IN_SRC];
__device__ __align__(16) __nv_bfloat16 g_XDH[(size_t)N_DST * IN_DST], g_XDL[(size_t)N_DST * IN_DST];
__device__ __align__(16) __nv_bfloat16 g_WSH[HID * IN_SRC], g_WSL[HID * IN_SRC];
__device__ __align__(16) __nv_bfloat16 g_WDH[HID * IN_DST], g_WDL[HID * IN_DST];
__device__ __align__(16) __nv_bfloat16 g_W1LH[HID * HID],  g_W1LL[HID * HID];
__device__ __align__(16) __nv_bfloat16 g_W1RH[HID * HID],  g_W1RL[HID * HID];
__device__ __align__(16) __nv_bfloat16 g_W2LH[OUTD * HID], g_W2LL[OUTD * HID];
__device__ __align__(16) __nv_bfloat16 g_W2RH[OUTD * HID], g_W2RL[OUTD * HID];
__device__ int   g_SRC[N_EDGES];
__device__ int   g_DSTL[N_EDGES];
__device__ int   g_IS64;
__device__ int   g_CNT[N_DST];
__device__ int   g_ROWPTR[N_DST + 1];
__device__ int   g_CURSOR[N_DST];
__device__ int   g_ESRC[N_EDGES];
__device__ float g_SUM[HID];
__device__ float g_SSQ[HID];
__device__ float g_SCALE[HID];
__device__ float g_SHIFT[HID];
__device__ int   g_TQ[4];

// ---------------- helpers ----------------
__device__ __forceinline__ uint32_t smem_u32(const void* p) {
    uint32_t a;
    asm("{ .reg .u64 t; cvta.to.shared.u64 t, %1; cvt.u32.u64 %0, t; }" : "=r"(a) : "l"(p));
    return a;
}
__device__ __forceinline__ void bulk_cp(uint32_t dst, const void* src, uint32_t bytes, uint32_t mbar) {
    asm volatile("cp.async.bulk.shared::cluster.global.mbarrier::complete_tx::bytes "
                 "[%0], [%1], %2, [%3];"
                 :: "r"(dst), "l"(src), "r"(bytes), "r"(mbar) : "memory");
}
#define MBAR_INIT(addr, cnt) \
    asm volatile("mbarrier.init.shared.b64 [%0], %1;" :: "r"(addr), "r"(cnt) : "memory")
#define MBAR_EXPECT(addr, bytes) \
    asm volatile("mbarrier.arrive.expect_tx.shared.b64 _, [%0], %1;" :: "r"(addr), "r"(bytes) : "memory")
#define MBAR_WAIT(addr, par) do { \
    uint32_t _m = (addr); uint32_t _p = (par); uint32_t _d; \
    asm volatile("{\n\t.reg .pred p;\n\tmbarrier.try_wait.parity.acquire.cta.shared::cta.b64 p, [%1], %2;\n\tselp.b32 %0,1,0,p;\n\t}" \
                 : "=r"(_d) : "r"(_m), "r"(_p) : "memory"); \
    while (!_d) { \
        asm volatile("{\n\t.reg .pred p;\n\tmbarrier.try_wait.parity.acquire.cta.shared::cta.b64 p, [%1], %2, 0x989680;\n\tselp.b32 %0,1,0,p;\n\t}" \
                     : "=r"(_d) : "r"(_m), "r"(_p) : "memory"); \
    } \
} while (0)
__device__ __forceinline__ void ldm_x4(uint32_t* r, uint32_t a) {
    asm volatile("ldmatrix.sync.aligned.m8n8.x4.shared.b16 {%0,%1,%2,%3}, [%4];"
                 : "=r"(r[0]), "=r"(r[1]), "=r"(r[2]), "=r"(r[3]) : "r"(a));
}
__device__ __forceinline__ void mma_bf16(float* d, const uint32_t* a, const uint32_t* b) {
    asm("mma.sync.aligned.m16n8k16.row.col.f32.bf16.bf16.f32 "
        "{%0,%1,%2,%3}, {%4,%5,%6,%7}, {%8,%9}, {%0,%1,%2,%3};"
        : "+f"(d[0]), "+f"(d[1]), "+f"(d[2]), "+f"(d[3])
        : "r"(a[0]), "r"(a[1]), "r"(a[2]), "r"(a[3]), "r"(b[0]), "r"(b[1]));
}
__device__ __forceinline__ void split_hl(float v, __nv_bfloat16& h, __nv_bfloat16& l) {
    h = __float2bfloat16(v);
    l = __float2bfloat16(v - __bfloat162float(h));
}

// ---------------- init ----------------
__global__ void k_init(const int* __restrict__ ei32) {
    int i = blockIdx.x * blockDim.x + threadIdx.x;
    if (i < N_DST) g_CNT[i] = 0;
    if (i < 4) g_TQ[i] = 0;
    if (blockIdx.x == 0 && threadIdx.x == 0) {
        int allzero = 1;
        for (int j = 0; j < 64; j++)
            if (ei32[2 * j + 1] != 0) { allzero = 0; break; }
        g_IS64 = allzero;
    }
}
__global__ void k_decode(const void* __restrict__ ei) {
    int e = blockIdx.x * blockDim.x + threadIdx.x;
    if (e >= N_EDGES) return;
    int s, d;
    if (g_IS64) {
        const long long* p = (const long long*)ei;
        s = (int)p[e]; d = (int)p[N_EDGES + e];
    } else {
        const int* p = (const int*)ei;
        s = p[e]; d = p[N_EDGES + e];
    }
    g_SRC[e] = s;
    g_DSTL[e] = d - N_SRC;
}
__global__ void k_count() {
    int e = blockIdx.x * blockDim.x + threadIdx.x;
    if (e < N_EDGES) {
        int d = g_DSTL[e];
        if (d >= 0 && d < N_DST) atomicAdd(&g_CNT[d], 1);
    }
}
__global__ void k_scan() {
    __shared__ int s[1024];
    const int t = threadIdx.x;
    if (t < HID) { g_SUM[t] = 0.f; g_SSQ[t] = 0.f; }
    const int base = t * 10;
    int vals[10];
    int local = 0;
#pragma unroll
    for (int i = 0; i < 10; i++) {
        int idx = base + i;
        int v = (idx < N_DST) ? g_CNT[idx] : 0;
        vals[i] = v; local += v;
    }
    s[t] = local;
    __syncthreads();
    for (int off = 1; off < 1024; off <<= 1) {
        int v = (t >= off) ? s[t - off] : 0;
        __syncthreads();
        s[t] += v;
        __syncthreads();
    }
    int run = (t == 0) ? 0 : s[t - 1];
#pragma unroll
    for (int i = 0; i < 10; i++) {
        int idx = base + i;
        if (idx < N_DST) { g_ROWPTR[idx] = run; g_CURSOR[idx] = run; run += vals[i]; }
    }
    if (t == 1023) g_ROWPTR[N_DST] = s[1023];
}
__global__ void k_fill() {
    int e = blockIdx.x * blockDim.x + threadIdx.x;
    if (e < N_EDGES) {
        int d = g_DSTL[e];
        int s = g_SRC[e];
        if (d >= 0 && d < N_DST && s >= 0 && s < N_TOT) {
            int pos = atomicAdd(&g_CURSOR[d], 1);
            if (pos < N_EDGES) g_ESRC[pos] = s;
        }
    }
}

// ---------------- batched fp32 -> (hi,lo) conversion ----------------
struct ConvTab {
    const float* s[8];
    __nv_bfloat16* h[8];
    __nv_bfloat16* l[8];
    int end[8];
};
__global__ void k_conv_all(ConvTab tb) {
    int i = blockIdx.x * blockDim.x + threadIdx.x;
    if (i >= tb.end[7]) return;
    int sg = 0;
#pragma unroll
    for (int j = 0; j < 7; j++) sg += (i >= tb.end[j]);
    int base = sg ? tb.end[sg - 1] : 0;
    int off = i - base;
    float4 v = ((const float4*)tb.s[sg])[off];
    __nv_bfloat16 hx, hy, hz, hw, lx, ly, lz, lw;
    split_hl(v.x, hx, lx); split_hl(v.y, hy, ly);
    split_hl(v.z, hz, lz); split_hl(v.w, hw, lw);
    __nv_bfloat162 h01; h01.x = hx; h01.y = hy;
    __nv_bfloat162 h23; h23.x = hz; h23.y = hw;
    __nv_bfloat162 l01; l01.x = lx; l01.y = ly;
    __nv_bfloat162 l23; l23.x = lz; l23.y = lw;
    ((__nv_bfloat162*)tb.h[sg])[2 * off] = h01; ((__nv_bfloat162*)tb.h[sg])[2 * off + 1] = h23;
    ((__nv_bfloat162*)tb.l[sg])[2 * off] = l01; ((__nv_bfloat162*)tb.l[sg])[2 * off + 1] = l23;
}

// ---------------- segment mean ----------------
__global__ void k_aggregate(const __nv_bfloat16* __restrict__ Xh, const __nv_bfloat16* __restrict__ Xl,
                            __nv_bfloat16* __restrict__ Mh, __nv_bfloat16* __restrict__ Ml) {
    const int d = blockIdx.x;
    const int t = threadIdx.x;
    const int beg = g_ROWPTR[d];
    const int end = g_ROWPTR[d + 1];
    float a0 = 0.f, a1 = 0.f, a2 = 0.f, a3 = 0.f;
    float b0 = 0.f, b1 = 0.f, b2 = 0.f, b3 = 0.f;
    int e = beg;
    for (; e + 1 < end; e += 2) {
        size_t o0 = (size_t)g_ESRC[e] * HID + t * 4;
        size_t o1 = (size_t)g_ESRC[e + 1] * HID + t * 4;
        __nv_bfloat162 h0a = *(const __nv_bfloat162*)(Xh + o0);
        __nv_bfloat162 h0b = *(const __nv_bfloat162*)(Xh + o0 + 2);
        __nv_bfloat162 l0a = *(const __nv_bfloat162*)(Xl + o0);
        __nv_bfloat162 l0b = *(const __nv_bfloat162*)(Xl + o0 + 2);
        __nv_bfloat162 h1a = *(const __nv_bfloat162*)(Xh + o1);
        __nv_bfloat162 h1b = *(const __nv_bfloat162*)(Xh + o1 + 2);
        __nv_bfloat162 l1a = *(const __nv_bfloat162*)(Xl + o1);
        __nv_bfloat162 l1b = *(const __nv_bfloat162*)(Xl + o1 + 2);
        float2 f;
        f = __bfloat1622float2(h0a); a0 += f.x; a1 += f.y;
        f = __bfloat1622float2(l0a); a0 += f.x; a1 += f.y;
        f = __bfloat1622float2(h0b); a2 += f.x; a3 += f.y;
        f = __bfloat1622float2(l0b); a2 += f.x; a3 += f.y;
        f = __bfloat1622float2(h1a); b0 += f.x; b1 += f.y;
        f = __bfloat1622float2(l1a); b0 += f.x; b1 += f.y;
        f = __bfloat1622float2(h1b); b2 += f.x; b3 += f.y;
        f = __bfloat1622float2(l1b); b2 += f.x; b3 += f.y;
    }
    if (e < end) {
        size_t o0 = (size_t)g_ESRC[e] * HID + t * 4;
        __nv_bfloat162 h0a = *(const __nv_bfloat162*)(Xh + o0);
        __nv_bfloat162 h0b = *(const __nv_bfloat162*)(Xh + o0 + 2);
        __nv_bfloat162 l0a = *(const __nv_bfloat162*)(Xl + o0);
        __nv_bfloat162 l0b = *(const __nv_bfloat162*)(Xl + o0 + 2);
        float2 f;
        f = __bfloat1622float2(h0a); a0 += f.x; a1 += f.y;
        f = __bfloat1622float2(l0a); a0 += f.x; a1 += f.y;
        f = __bfloat1622float2(h0b); a2 += f.x; a3 += f.y;
        f = __bfloat1622float2(l0b); a2 += f.x; a3 += f.y;
    }
    float inv = 1.0f / fmaxf((float)(end - beg), 1.0f);
    float m0 = (a0 + b0) * inv, m1 = (a1 + b1) * inv;
    float m2 = (a2 + b2) * inv, m3 = (a3 + b3) * inv;
    size_t o = (size_t)d * HID + t * 4;
    __nv_bfloat16 h0, h1, h2, h3, l0, l1, l2, l3;
    split_hl(m0, h0, l0); split_hl(m1, h1, l1);
    split_hl(m2, h2, l2); split_hl(m3, h3, l3);
    __nv_bfloat162 ha; ha.x = h0; ha.y = h1;
    __nv_bfloat162 hb; hb.x = h2; hb.y = h3;
    __nv_bfloat162 la; la.x = l0; la.y = l1;
    __nv_bfloat162 lb; lb.x = l2; lb.y = l3;
    *(__nv_bfloat162*)(Mh + o) = ha; *(__nv_bfloat162*)(Mh + o + 2) = hb;
    *(__nv_bfloat162*)(Ml + o) = la; *(__nv_bfloat162*)(Ml + o + 2) = lb;
}

// ---------------- persistent fused dual-term GEMM (bulk-copy loads) ----------------
// R9 geometry (128x128 tiles, 8 warps, 2m x 4n, BK=64), but global->smem uses
// cp.async.bulk 128B-row copies: 512 LSU ops/chunk instead of 4096 cp.async.
#define ROWB 144
#define TILE_SB (128 * ROWB)       // 18432
#define STAGE_SB (4 * TILE_SB)     // 73728
#define NSTAGE 2
#define BNOFF (NSTAGE * STAGE_SB)  // 147456
#define MBAROFF (BNOFF + 1024)     // 2 x 8B mbarriers
#define NEXTOFF (MBAROFF + 16)
#define GSMEM (NEXTOFF + 16)
#define GTHR 256
#define NSM 148
#define CHUNK_BYTES 65536u

__global__ void __launch_bounds__(GTHR, 1)
k_bgemm(const __nv_bfloat16* __restrict__ a0h_r0, const __nv_bfloat16* __restrict__ a0l_r0,
        const __nv_bfloat16* __restrict__ w0h_r0, const __nv_bfloat16* __restrict__ w0l_r0, int K0_r0,
        const __nv_bfloat16* __restrict__ a0h_r1, const __nv_bfloat16* __restrict__ a0l_r1,
        const __nv_bfloat16* __restrict__ w0h_r1, const __nv_bfloat16* __restrict__ w0l_r1, int K0_r1,
        const __nv_bfloat16* __restrict__ a1h, const __nv_bfloat16* __restrict__ a1l,
        const __nv_bfloat16* __restrict__ w1h, const __nv_bfloat16* __restrict__ w1l, int K1,
        const float* __restrict__ bias_r0, const float* __restrict__ bias_r1,
        float* __restrict__ Cf, __nv_bfloat16* __restrict__ Ch, __nv_bfloat16* __restrict__ Cl,
        int N, int do_bn, int nx, int NT, int lfr, int qslot)
{
    extern __shared__ __align__(16) char smem[];
    const uint32_t sb = smem_u32(smem);
    const int tid = threadIdx.x;
    const int lane = tid & 31;
    const int wid = tid >> 5;
    const int wm = wid & 1;
    const int wn = wid >> 1;
    volatile int* nextp = (volatile int*)(smem + NEXTOFF);
    float* smS = (float*)(smem + BNOFF);
    float* smQ = smS + 128;
    const uint32_t mbar0 = sb + MBAROFF;

    if (tid == 0) {
        MBAR_INIT(mbar0, 1);
        MBAR_INIT(mbar0 + 8, 1);
        *nextp = atomicAdd(&g_TQ[qslot], 1);
    }
    __syncthreads();

    auto geom = [&](int t, int& region, int& bml, int& bn, int& ncT, int& nc0) {
        int iy = t / nx, ix = t - iy * nx;
        int r = (iy < YTILES) ? lfr : (1 - lfr);
        region = r;
        bml = (iy < YTILES ? iy : iy - YTILES) * 128;
        bn = ix * 128;
        int K0 = r ? K0_r1 : K0_r0;
        nc0 = K0 >> 6;
        ncT = nc0 + ((r && K1 > 0) ? (K1 >> 6) : 0);
    };

    // 512 row-copies of 128B each; OOB A-rows read tile row 0 (masked later).
    auto load_chunk = [&](int region, int bml, int bn, int nc0, int c, int slot) {
        const __nv_bfloat16 *ah, *al, *wh, *wl;
        int Ks, kof;
        if (c < nc0) {
            ah = region ? a0h_r1 : a0h_r0; al = region ? a0l_r1 : a0l_r0;
            wh = region ? w0h_r1 : w0h_r0; wl = region ? w0l_r1 : w0l_r0;
            Ks = region ? K0_r1 : K0_r0; kof = c << 6;
        } else {
            ah = a1h; al = a1l; wh = w1h; wl = w1l; Ks = K1; kof = (c - nc0) << 6;
        }
        uint32_t st = sb + (uint32_t)slot * STAGE_SB;
        uint32_t mb = mbar0 + (uint32_t)slot * 8;
        if (tid == 0) MBAR_EXPECT(mb, CHUNK_BYTES);
        for (int i = tid; i < 512; i += GTHR) {
            int tile = i >> 7;            // 0 Ah, 1 Al, 2 Wh, 3 Wl
            int r = i & 127;
            uint32_t dst = st + (uint32_t)tile * TILE_SB + (uint32_t)r * ROWB;
            const __nv_bfloat16* src;
            if (tile < 2) {
                int gml = bml + r;
                if (gml >= MREG) gml = bml;     // safe filler row
                src = (tile == 0 ? ah : al) + (size_t)gml * Ks + kof;
            } else {
                src = (tile == 2 ? wh : wl) + (size_t)(bn + r) * Ks + kof;
            }
            bulk_cp(dst, src, 128, mb);
        }
    };

    int t = *nextp;
    if (t >= NT) return;

    int region, bml, bn, ncT, nc0;
    geom(t, region, bml, bn, ncT, nc0);
    load_chunk(region, bml, bn, nc0, 0, 0);
    load_chunk(region, bml, bn, nc0, 1, 1);
    int ph[2] = {0, 0};

    while (true) {
        float acc[4][4][4];
#pragma unroll
        for (int i = 0; i < 4; i++)
#pragma unroll
            for (int j = 0; j < 4; j++)
#pragma unroll
                for (int q = 0; q < 4; q++) acc[i][j][q] = 0.f;

        for (int c = 0; c < ncT; c++) {
            const int slot = c & 1;
            MBAR_WAIT(mbar0 + slot * 8, ph[slot] & 1);
            ph[slot]++;
            __syncthreads();
            if (c == 0 && tid == 0) *nextp = atomicAdd(&g_TQ[qslot], 1);

            const uint32_t st = sb + (uint32_t)slot * STAGE_SB;
#pragma unroll
            for (int ks = 0; ks < 4; ks++) {
                uint32_t ah[4][4], al[4][4], bh[4][2], bl[4][2];
                const int arow = wm * 64 + ((lane & 8) ? 8 : 0) + (lane & 7);
                const int acol = ks * 16 + ((lane & 16) ? 8 : 0);
#pragma unroll
                for (int mt = 0; mt < 4; mt++) {
                    uint32_t ad = st + (uint32_t)(arow + mt * 16) * ROWB + acol * 2;
                    ldm_x4(ah[mt], ad);
                    ldm_x4(al[mt], ad + TILE_SB);
                }
                const int brow = ((lane & 16) ? 8 : 0) + (lane & 7);
                const int bcol = ks * 16 + ((lane & 8) ? 8 : 0);
#pragma unroll
                for (int pr = 0; pr < 2; pr++) {
                    uint32_t tmp[4];
                    uint32_t bd = st + 2 * TILE_SB + (uint32_t)(wn * 32 + pr * 16 + brow) * ROWB + bcol * 2;
                    ldm_x4(tmp, bd);
                    bh[2 * pr][0] = tmp[0]; bh[2 * pr][1] = tmp[1];
                    bh[2 * pr + 1][0] = tmp[2]; bh[2 * pr + 1][1] = tmp[3];
                    ldm_x4(tmp, bd + TILE_SB);
                    bl[2 * pr][0] = tmp[0]; bl[2 * pr][1] = tmp[1];
                    bl[2 * pr + 1][0] = tmp[2]; bl[2 * pr + 1][1] = tmp[3];
                }
#pragma unroll
                for (int mt = 0; mt < 4; mt++)
#pragma unroll
                    for (int nt = 0; nt < 4; nt++)
                        mma_bf16(acc[mt][nt], ah[mt], bh[nt]);
#pragma unroll
                for (int mt = 0; mt < 4; mt++)
#pragma unroll
                    for (int nt = 0; nt < 4; nt++)
                        mma_bf16(acc[mt][nt], ah[mt], bl[nt]);
#pragma unroll
                for (int mt = 0; mt < 4; mt++)
#pragma unroll
                    for (int nt = 0; nt < 4; nt++)
                        mma_bf16(acc[mt][nt], al[mt], bh[nt]);
            }
            __syncthreads();   // all reads of this slot done before refilling it

            int pc = c + 2;
            if (pc < ncT) {
                load_chunk(region, bml, bn, nc0, pc, slot);
            } else {
                int tn = *nextp;  // written at c==0, published by the c-loop syncs (ncT >= 4)
                if (tn < NT) {
                    int r2, b2, n2, nt2, nc02;
                    geom(tn, r2, b2, n2, nt2, nc02);
                    load_chunk(r2, b2, n2, nc02, pc - ncT, slot);
                }
            }
        }

        // ---- epilogue ----
        if (do_bn) {
            if (tid < 128) { smS[tid] = 0.f; smQ[tid] = 0.f; }
            __syncthreads();
        }
        const float* bias = region ? bias_r1 : bias_r0;
        const int g = lane >> 2, tg = lane & 3;
        float bnS[4][2], bnQ[4][2];
#pragma unroll
        for (int nt = 0; nt < 4; nt++) { bnS[nt][0] = bnS[nt][1] = 0.f; bnQ[nt][0] = bnQ[nt][1] = 0.f; }

#pragma unroll
        for (int mt = 0; mt < 4; mt++)
#pragma unroll
            for (int h = 0; h < 2; h++) {
                const int gml = bml + wm * 64 + mt * 16 + g + h * 8;
                if (gml >= MREG) continue;
                const int grow = region * MREG + gml;
#pragma unroll
                for (int nt = 0; nt < 4; nt++) {
                    const int gn = bn + wn * 32 + nt * 8 + tg * 2;
                    float v0 = acc[mt][nt][h * 2 + 0];
                    float v1 = acc[mt][nt][h * 2 + 1];
                    if (bias) { v0 += __ldg(bias + gn); v1 += __ldg(bias + gn + 1); }
                    if (Cf) {
                        float2 vv; vv.x = v0; vv.y = v1;
                        *(float2*)(Cf + (size_t)grow * N + gn) = vv;
                    }
                    if (Ch) {
                        __nv_bfloat16 h0, h1, l0, l1;
                        split_hl(v0, h0, l0); split_hl(v1, h1, l1);
                        __nv_bfloat162 hp; hp.x = h0; hp.y = h1;
                        __nv_bfloat162 lp; lp.x = l0; lp.y = l1;
                        *(__nv_bfloat162*)(Ch + (size_t)grow * N + gn) = hp;
                        *(__nv_bfloat162*)(Cl + (size_t)grow * N + gn) = lp;
                    }
                    if (do_bn) {
                        bnS[nt][0] += v0; bnQ[nt][0] += v0 * v0;
                        bnS[nt][1] += v1; bnQ[nt][1] += v1 * v1;
                    }
                }
            }

        if (do_bn) {
#pragma unroll
            for (int nt = 0; nt < 4; nt++)
#pragma unroll
                for (int q = 0; q < 2; q++) {
                    float s = bnS[nt][q], qq = bnQ[nt][q];
#pragma unroll
                    for (int off = 4; off < 32; off <<= 1) {
                        s += __shfl_xor_sync(0xffffffffu, s, off);
                        qq += __shfl_xor_sync(0xffffffffu, qq, off);
                    }
                    if (g == 0) {
                        int cl = wn * 32 + nt * 8 + tg * 2 + q;
                        atomicAdd(&smS[cl], s);
                        atomicAdd(&smQ[cl], qq);
                    }
                }
            __syncthreads();
            if (tid < 128) {
                atomicAdd(&g_SUM[bn + tid], smS[tid]);
                atomicAdd(&g_SSQ[bn + tid], smQ[tid]);
            }
        }

        int tn = *nextp;
        if (tn >= NT) break;
        t = tn;
        geom(t, region, bml, bn, ncT, nc0);
    }
}

// ---------------- BatchNorm finalize + apply ----------------
__global__ void k_bnfinal(const float* __restrict__ gamma, const float* __restrict__ beta) {
    int c = threadIdx.x;
    if (c < HID) {
        float mu = g_SUM[c] * (1.0f / (float)N_TOT);
        float var = g_SSQ[c] * (1.0f / (float)N_TOT) - mu * mu;
        float sc = gamma[c] * rsqrtf(var + EPS);
        g_SCALE[c] = sc;
        g_SHIFT[c] = beta[c] - mu * sc;
    }
}
__global__ void k_bnapply() {
    size_t i = (size_t)blockIdx.x * blockDim.x + threadIdx.x;
    size_t base = i * 8;
    if (base >= (size_t)N_TOT * HID) return;
    int c = (int)(base & (HID - 1));
#pragma unroll
    for (int j = 0; j < 8; j += 2) {
        __nv_bfloat162 hp = *(const __nv_bfloat162*)(g_X1H + base + j);
        __nv_bfloat162 lp = *(const __nv_bfloat162*)(g_X1L + base + j);
        float2 hf = __bfloat1622float2(hp);
        float2 lf = __bfloat1622float2(lp);
        float x0 = hf.x + lf.x, x1 = hf.y + lf.y;
        float y0 = fmaxf(fmaf(x0, g_SCALE[c + j], g_SHIFT[c + j]), 0.f);
        float y1 = fmaxf(fmaf(x1, g_SCALE[c + j + 1], g_SHIFT[c + j + 1]), 0.f);
        __nv_bfloat16 h0, h1, l0, l1;
        split_hl(y0, h0, l0); split_hl(y1, h1, l1);
        __nv_bfloat162 ho; ho.x = h0; ho.y = h1;
        __nv_bfloat162 lo; lo.x = l0; lo.y = l1;
        *(__nv_bfloat162*)(g_AH + base + j) = ho;
        *(__nv_bfloat162*)(g_AL + base + j) = lo;
    }
}

// ---------------- launch ----------------
extern "C" void kernel_launch(void* const* d_in, const int* in_sizes, int n_in,
                              void* d_out, int out_size) {
    const float* x_src = (const float*)d_in[0];
    const float* x_dst = (const float*)d_in[1];
    const float* W_src = (const float*)d_in[2];
    const float* b_src = (const float*)d_in[3];
    const float* W_dst = (const float*)d_in[4];
    const float* b_dst = (const float*)d_in[5];
    const float* W1l   = (const float*)d_in[6];
    const float* b1    = (const float*)d_in[7];
    const float* W1r   = (const float*)d_in[8];
    const float* W2l   = (const float*)d_in[9];
    const float* b2    = (const float*)d_in[10];
    const float* W2r   = (const float*)d_in[11];
    const float* gamma = (const float*)d_in[12];
    const float* beta  = (const float*)d_in[13];
    const void*  ei    = (const void*)d_in[14];
    float* out = (float*)d_out;

    static int smem_set = 0;
    if (!smem_set) {
        cudaFuncSetAttribute(k_bgemm, cudaFuncAttributeMaxDynamicSharedMemorySize, GSMEM);
        smem_set = 1;
    }

    __nv_bfloat16 *AH, *AL, *X1H, *X1L, *MH, *ML, *XSH, *XSL, *XDH, *XDL;
    __nv_bfloat16 *WSH, *WSL, *WDH, *WDL, *W1LH, *W1LL, *W1RH, *W1RL, *W2LH, *W2LL, *W2RH, *W2RL;
    cudaGetSymbolAddress((void**)&AH, g_AH);   cudaGetSymbolAddress((void**)&AL, g_AL);
    cudaGetSymbolAddress((void**)&X1H, g_X1H); cudaGetSymbolAddress((void**)&X1L, g_X1L);
    cudaGetSymbolAddress((void**)&MH, g_MH);   cudaGetSymbolAddress((void**)&ML, g_ML);
    cudaGetSymbolAddress((void**)&XSH, g_XSH); cudaGetSymbolAddress((void**)&XSL, g_XSL);
    cudaGetSymbolAddress((void**)&XDH, g_XDH); cudaGetSymbolAddress((void**)&XDL, g_XDL);
    cudaGetSymbolAddress((void**)&WSH, g_WSH);  cudaGetSymbolAddress((void**)&WSL, g_WSL);
    cudaGetSymbolAddress((void**)&WDH, g_WDH);  cudaGetSymbolAddress((void**)&WDL, g_WDL);
    cudaGetSymbolAddress((void**)&W1LH, g_W1LH); cudaGetSymbolAddress((void**)&W1LL, g_W1LL);
    cudaGetSymbolAddress((void**)&W1RH, g_W1RH); cudaGetSymbolAddress((void**)&W1RL, g_W1RL);
    cudaGetSymbolAddress((void**)&W2LH, g_W2LH); cudaGetSymbolAddress((void**)&W2LL, g_W2LL);
    cudaGetSymbolAddress((void**)&W2RH, g_W2RH); cudaGetSymbolAddress((void**)&W2RL, g_W2RL);

    k_init<<<(N_DST + 255) / 256, 256>>>((const int*)ei);
    k_decode<<<(N_EDGES + 255) / 256, 256>>>(ei);
    ConvTab tb;
    const float* srcs[8] = {W_src, W_dst, W1l, W1r, W2l, W2r, x_src, x_dst};
    __nv_bfloat16* hs[8] = {WSH, WDH, W1LH, W1RH, W2LH, W2RH, XSH, XDH};
    __nv_bfloat16* ls[8] = {WSL, WDL, W1LL, W1RL, W2LL, W2RL, XSL, XDL};
    int ns[8] = {HID * IN_SRC, HID * IN_DST, HID * HID, HID * HID, OUTD * HID, OUTD * HID,
                 N_SRC * IN_SRC, N_DST * IN_DST};
    int cum = 0;
    for (int j = 0; j < 8; j++) {
        tb.s[j] = srcs[j]; tb.h[j] = hs[j]; tb.l[j] = ls[j];
        cum += ns[j] / 4; tb.end[j] = cum;
    }
    k_conv_all<<<(cum + 255) / 256, 256>>>(tb);

    // fused projection GEMM -> AH/AL
    k_bgemm<<<NSM, GTHR, GSMEM>>>(XSH, XSL, WSH, WSL, IN_SRC,
                                  XDH, XDL, WDH, WDL, IN_DST,
                                  nullptr, nullptr, nullptr, nullptr, 0,
                                  b_src, b_dst,
                                  nullptr, AH, AL, HID, 0,
                                  HID / 128, (HID / 128) * 2 * YTILES, 0, 0);

    // CSR build
    k_count<<<(N_EDGES + 255) / 256, 256>>>();
    k_scan<<<1, 1024>>>();
    k_fill<<<(N_EDGES + 255) / 256, 256>>>();

    // layer 1
    k_aggregate<<<N_DST, 128>>>(AH, AL, MH, ML);
    k_bgemm<<<NSM, GTHR, GSMEM>>>(AH, AL, W1RH, W1RL, HID,
                                  AH + (size_t)N_SRC * HID, AL + (size_t)N_SRC * HID, W1RH, W1RL, HID,
                                  MH, ML, W1LH, W1LL, HID,
                                  b1, b1,
                                  nullptr, X1H, X1L, HID, 1,
                                  HID / 128, (HID / 128) * 2 * YTILES, 1, 1);

    // BN finalize + apply (+ReLU)
    k_bnfinal<<<1, 512>>>(gamma, beta);
    k_bnapply<<<(int)(((size_t)N_TOT * HID / 8 + 255) / 256), 256>>>();

    // layer 2
    k_aggregate<<<N_DST, 128>>>(AH, AL, MH, ML);
    k_bgemm<<<NSM, GTHR, GSMEM>>>(AH, AL, W2RH, W2RL, HID,
                                  AH + (size_t)N_SRC * HID, AL + (size_t)N_SRC * HID, W2RH, W2RL, HID,
                                  MH, ML, W2LH, W2LL, HID,
                                  b2, b2,
                                  out, nullptr, nullptr, OUTD, 0,
                                  OUTD / 128, (OUTD / 128) * 2 * YTILES, 1, 2);
}

// round 12
// speedup vs baseline: 1.6796x; 1.6796x over previous
#include <cuda_runtime.h>
#include <cuda_fp16.h>
#include <math.h>
#include <stdint.h>

#define N_SRC   10000
#define N_DST   10000
#define N_TOT   20000
#define IN_SRC  512
#define IN_DST  256
#define HID     512
#define OUTD    256
#define N_EDGES 160000
#define EPS     1e-5f
#define MREG    10000
#define YTILES  79

// ---------------- device scratch (fp16 hi/lo activations, fp16 single weights) --------
__device__ __align__(16) __half g_AH[(size_t)N_TOT * HID];
__device__ __align__(16) __half g_AL[(size_t)N_TOT * HID];
__device__ __align__(16) __half g_X1H[(size_t)N_TOT * HID];
__device__ __align__(16) __half g_X1L[(size_t)N_TOT * HID];
__device__ __align__(16) __half g_MH[(size_t)N_DST * HID];
__device__ __align__(16) __half g_ML[(size_t)N_DST * HID];
__device__ __align__(16) __half g_XSH[(size_t)N_SRC * IN_SRC], g_XSL[(size_t)N_SRC * IN_SRC];
__device__ __align__(16) __half g_XDH[(size_t)N_DST * IN_DST], g_XDL[(size_t)N_DST * IN_DST];
__device__ __align__(16) __half g_WS[HID * IN_SRC];
__device__ __align__(16) __half g_WD[HID * IN_DST];
__device__ __align__(16) __half g_W1L[HID * HID];
__device__ __align__(16) __half g_W1R[HID * HID];
__device__ __align__(16) __half g_W2L[OUTD * HID];
__device__ __align__(16) __half g_W2R[OUTD * HID];
__device__ int   g_SRC[N_EDGES];
__device__ int   g_DSTL[N_EDGES];
__device__ int   g_IS64;
__device__ int   g_CNT[N_DST];
__device__ int   g_ROWPTR[N_DST + 1];
__device__ int   g_CURSOR[N_DST];
__device__ int   g_ESRC[N_EDGES];
__device__ float g_SUM[HID];
__device__ float g_SSQ[HID];
__device__ float g_SCALE[HID];
__device__ float g_SHIFT[HID];
__device__ int   g_TQ[4];

// ---------------- helpers ----------------
__device__ __forceinline__ uint32_t smem_u32(const void* p) {
    uint32_t a;
    asm("{ .reg .u64 t; cvta.to.shared.u64 t, %1; cvt.u32.u64 %0, t; }" : "=r"(a) : "l"(p));
    return a;
}
__device__ __forceinline__ void cpa(uint32_t d, const void* s, int sz) {
    asm volatile("cp.async.cg.shared.global [%0], [%1], 16, %2;"
                 :: "r"(d), "l"(s), "r"(sz) : "memory");
}
__device__ __forceinline__ void ldm_x4(uint32_t* r, uint32_t a) {
    asm volatile("ldmatrix.sync.aligned.m8n8.x4.shared.b16 {%0,%1,%2,%3}, [%4];"
                 : "=r"(r[0]), "=r"(r[1]), "=r"(r[2]), "=r"(r[3]) : "r"(a));
}
__device__ __forceinline__ void mma_f16(float* d, const uint32_t* a, const uint32_t* b) {
    asm("mma.sync.aligned.m16n8k16.row.col.f32.f16.f16.f32 "
        "{%0,%1,%2,%3}, {%4,%5,%6,%7}, {%8,%9}, {%0,%1,%2,%3};"
        : "+f"(d[0]), "+f"(d[1]), "+f"(d[2]), "+f"(d[3])
        : "r"(a[0]), "r"(a[1]), "r"(a[2]), "r"(a[3]), "r"(b[0]), "r"(b[1]));
}
__device__ __forceinline__ void split_hl(float v, __half& h, __half& l) {
    h = __float2half_rn(v);
    l = __float2half_rn(v - __half2float(h));
}

// ---------------- init ----------------
__global__ void k_init(const int* __restrict__ ei32) {
    int i = blockIdx.x * blockDim.x + threadIdx.x;
    if (i < N_DST) g_CNT[i] = 0;
    if (i < 4) g_TQ[i] = 0;
    if (blockIdx.x == 0 && threadIdx.x == 0) {
        int allzero = 1;
        for (int j = 0; j < 64; j++)
            if (ei32[2 * j + 1] != 0) { allzero = 0; break; }
        g_IS64 = allzero;
    }
}
__global__ void k_decode(const void* __restrict__ ei) {
    int e = blockIdx.x * blockDim.x + threadIdx.x;
    if (e >= N_EDGES) return;
    int s, d;
    if (g_IS64) {
        const long long* p = (const long long*)ei;
        s = (int)p[e]; d = (int)p[N_EDGES + e];
    } else {
        const int* p = (const int*)ei;
        s = p[e]; d = p[N_EDGES + e];
    }
    g_SRC[e] = s;
    g_DSTL[e] = d - N_SRC;
}
__global__ void k_count() {
    int e = blockIdx.x * blockDim.x + threadIdx.x;
    if (e < N_EDGES) {
        int d = g_DSTL[e];
        if (d >= 0 && d < N_DST) atomicAdd(&g_CNT[d], 1);
    }
}
__global__ void k_scan() {
    __shared__ int s[1024];
    const int t = threadIdx.x;
    if (t < HID) { g_SUM[t] = 0.f; g_SSQ[t] = 0.f; }
    const int base = t * 10;
    int vals[10];
    int local = 0;
#pragma unroll
    for (int i = 0; i < 10; i++) {
        int idx = base + i;
        int v = (idx < N_DST) ? g_CNT[idx] : 0;
        vals[i] = v; local += v;
    }
    s[t] = local;
    __syncthreads();
    for (int off = 1; off < 1024; off <<= 1) {
        int v = (t >= off) ? s[t - off] : 0;
        __syncthreads();
        s[t] += v;
        __syncthreads();
    }
    int run = (t == 0) ? 0 : s[t - 1];
#pragma unroll
    for (int i = 0; i < 10; i++) {
        int idx = base + i;
        if (idx < N_DST) { g_ROWPTR[idx] = run; g_CURSOR[idx] = run; run += vals[i]; }
    }
    if (t == 1023) g_ROWPTR[N_DST] = s[1023];
}
__global__ void k_fill() {
    int e = blockIdx.x * blockDim.x + threadIdx.x;
    if (e < N_EDGES) {
        int d = g_DSTL[e];
        int s = g_SRC[e];
        if (d >= 0 && d < N_DST && s >= 0 && s < N_TOT) {
            int pos = atomicAdd(&g_CURSOR[d], 1);
            if (pos < N_EDGES) g_ESRC[pos] = s;
        }
    }
}

// ---------------- batched fp32 -> fp16 conversion (split when l != null) -------------
struct ConvTab {
    const float* s[8];
    __half* h[8];
    __half* l[8];
    int end[8];
};
__global__ void k_conv_all(ConvTab tb) {
    int i = blockIdx.x * blockDim.x + threadIdx.x;
    if (i >= tb.end[7]) return;
    int sg = 0;
#pragma unroll
    for (int j = 0; j < 7; j++) sg += (i >= tb.end[j]);
    int base = sg ? tb.end[sg - 1] : 0;
    int off = i - base;
    float4 v = ((const float4*)tb.s[sg])[off];
    if (tb.l[sg]) {
        __half hx, hy, hz, hw, lx, ly, lz, lw;
        split_hl(v.x, hx, lx); split_hl(v.y, hy, ly);
        split_hl(v.z, hz, lz); split_hl(v.w, hw, lw);
        __half2 h01 = __halves2half2(hx, hy);
        __half2 h23 = __halves2half2(hz, hw);
        __half2 l01 = __halves2half2(lx, ly);
        __half2 l23 = __halves2half2(lz, lw);
        ((__half2*)tb.h[sg])[2 * off] = h01; ((__half2*)tb.h[sg])[2 * off + 1] = h23;
        ((__half2*)tb.l[sg])[2 * off] = l01; ((__half2*)tb.l[sg])[2 * off + 1] = l23;
    } else {
        __half2 h01 = __halves2half2(__float2half_rn(v.x), __float2half_rn(v.y));
        __half2 h23 = __halves2half2(__float2half_rn(v.z), __float2half_rn(v.w));
        ((__half2*)tb.h[sg])[2 * off] = h01; ((__half2*)tb.h[sg])[2 * off + 1] = h23;
    }
}

// ---------------- segment mean ----------------
__global__ void k_aggregate(const __half* __restrict__ Xh, const __half* __restrict__ Xl,
                            __half* __restrict__ Mh, __half* __restrict__ Ml) {
    const int d = blockIdx.x;
    const int t = threadIdx.x;
    const int beg = g_ROWPTR[d];
    const int end = g_ROWPTR[d + 1];
    float a0 = 0.f, a1 = 0.f, a2 = 0.f, a3 = 0.f;
    float b0 = 0.f, b1 = 0.f, b2 = 0.f, b3 = 0.f;
    int e = beg;
    for (; e + 1 < end; e += 2) {
        size_t o0 = (size_t)g_ESRC[e] * HID + t * 4;
        size_t o1 = (size_t)g_ESRC[e + 1] * HID + t * 4;
        float2 f;
        f = __half22float2(*(const __half2*)(Xh + o0));     a0 += f.x; a1 += f.y;
        f = __half22float2(*(const __half2*)(Xl + o0));     a0 += f.x; a1 += f.y;
        f = __half22float2(*(const __half2*)(Xh + o0 + 2)); a2 += f.x; a3 += f.y;
        f = __half22float2(*(const __half2*)(Xl + o0 + 2)); a2 += f.x; a3 += f.y;
        f = __half22float2(*(const __half2*)(Xh + o1));     b0 += f.x; b1 += f.y;
        f = __half22float2(*(const __half2*)(Xl + o1));     b0 += f.x; b1 += f.y;
        f = __half22float2(*(const __half2*)(Xh + o1 + 2)); b2 += f.x; b3 += f.y;
        f = __half22float2(*(const __half2*)(Xl + o1 + 2)); b2 += f.x; b3 += f.y;
    }
    if (e < end) {
        size_t o0 = (size_t)g_ESRC[e] * HID + t * 4;
        float2 f;
        f = __half22float2(*(const __half2*)(Xh + o0));     a0 += f.x; a1 += f.y;
        f = __half22float2(*(const __half2*)(Xl + o0));     a0 += f.x; a1 += f.y;
        f = __half22float2(*(const __half2*)(Xh + o0 + 2)); a2 += f.x; a3 += f.y;
        f = __half22float2(*(const __half2*)(Xl + o0 + 2)); a2 += f.x; a3 += f.y;
    }
    float inv = 1.0f / fmaxf((float)(end - beg), 1.0f);
    float m0 = (a0 + b0) * inv, m1 = (a1 + b1) * inv;
    float m2 = (a2 + b2) * inv, m3 = (a3 + b3) * inv;
    size_t o = (size_t)d * HID + t * 4;
    __half h0, h1, h2, h3, l0, l1, l2, l3;
    split_hl(m0, h0, l0); split_hl(m1, h1, l1);
    split_hl(m2, h2, l2); split_hl(m3, h3, l3);
    *(__half2*)(Mh + o) = __halves2half2(h0, h1);
    *(__half2*)(Mh + o + 2) = __halves2half2(h2, h3);
    *(__half2*)(Ml + o) = __halves2half2(l0, l1);
    *(__half2*)(Ml + o + 2) = __halves2half2(l2, l3);
}

// ---------------- persistent fused dual-term GEMM (fp16, 2 MMA terms) ----------------
// 128x128 tiles, 8 warps (2m x 4n), BK=64, 3 stages, stage = {Ah, Al, W} tiles.
#define ROWB 144
#define TILE_SB (128 * ROWB)       // 18432
#define STAGE_SB (3 * TILE_SB)     // 55296
#define NSTAGE 3
#define BNOFF (NSTAGE * STAGE_SB)  // 165888
#define NEXTOFF (BNOFF + 1024)
#define GSMEM (NEXTOFF + 32)       // 166944
#define GTHR 256
#define NSM 148

__global__ void __launch_bounds__(GTHR, 1)
k_bgemm(const __half* __restrict__ a0h_r0, const __half* __restrict__ a0l_r0,
        const __half* __restrict__ w0_r0, int K0_r0,
        const __half* __restrict__ a0h_r1, const __half* __restrict__ a0l_r1,
        const __half* __restrict__ w0_r1, int K0_r1,
        const __half* __restrict__ a1h, const __half* __restrict__ a1l,
        const __half* __restrict__ w1, int K1,
        const float* __restrict__ bias_r0, const float* __restrict__ bias_r1,
        float* __restrict__ Cf, __half* __restrict__ Ch, __half* __restrict__ Cl,
        int N, int do_bn, int nx, int NT, int lfr, int qslot)
{
    extern __shared__ __align__(16) char smem[];
    const uint32_t sb = smem_u32(smem);
    const int tid = threadIdx.x;
    const int lane = tid & 31;
    const int wid = tid >> 5;
    const int wm = wid & 1;
    const int wn = wid >> 1;
    volatile int* nextp = (volatile int*)(smem + NEXTOFF);
    float* smS = (float*)(smem + BNOFF);
    float* smQ = smS + 128;

    auto geom = [&](int t, int& region, int& bml, int& bn, int& ncT, int& nc0) {
        int iy = t / nx, ix = t - iy * nx;
        int r = (iy < YTILES) ? lfr : (1 - lfr);
        region = r;
        bml = (iy < YTILES ? iy : iy - YTILES) * 128;
        bn = ix * 128;
        int K0 = r ? K0_r1 : K0_r0;
        nc0 = K0 >> 6;
        ncT = nc0 + ((r && K1 > 0) ? (K1 >> 6) : 0);
    };

    auto load_chunk = [&](int region, int bml, int bn, int nc0, int c, int slot) {
        const __half *ah, *al, *wp;
        int Ks, kof;
        if (c < nc0) {
            ah = region ? a0h_r1 : a0h_r0; al = region ? a0l_r1 : a0l_r0;
            wp = region ? w0_r1 : w0_r0;
            Ks = region ? K0_r1 : K0_r0; kof = c << 6;
        } else {
            ah = a1h; al = a1l; wp = w1; Ks = K1; kof = (c - nc0) << 6;
        }
        uint32_t st = sb + (uint32_t)slot * STAGE_SB;
        for (int i = tid; i < 1024; i += GTHR) {
            int r = i >> 3, cc = i & 7;
            uint32_t so = st + r * ROWB + cc * 16;
            int gml = bml + r;
            int sz = (gml < MREG) ? 16 : 0;
            size_t go = (size_t)(sz ? gml : 0) * Ks + kof + cc * 8;
            cpa(so, ah + go, sz);
            cpa(so + TILE_SB, al + go, sz);
            size_t gw = (size_t)(bn + r) * Ks + kof + cc * 8;
            cpa(so + 2 * TILE_SB, wp + gw, 16);
        }
        asm volatile("cp.async.commit_group;" ::: "memory");
    };

    if (tid == 0) *nextp = atomicAdd(&g_TQ[qslot], 1);
    __syncthreads();
    int t = *nextp;
    if (t >= NT) return;

    int region, bml, bn, ncT, nc0;
    geom(t, region, bml, bn, ncT, nc0);
    load_chunk(region, bml, bn, nc0, 0, 0);
    load_chunk(region, bml, bn, nc0, 1, 1);
    int gidx = 0;

    while (true) {
        float acc[4][4][4];
#pragma unroll
        for (int i = 0; i < 4; i++)
#pragma unroll
            for (int j = 0; j < 4; j++)
#pragma unroll
                for (int q = 0; q < 4; q++) acc[i][j][q] = 0.f;

        for (int c = 0; c < ncT; c++) {
            asm volatile("cp.async.wait_group 1;" ::: "memory");
            __syncthreads();
            if (c == 0 && tid == 0) *nextp = atomicAdd(&g_TQ[qslot], 1);
            {
                int pc = c + 2;
                int pslot = (gidx + 2) % NSTAGE;
                if (pc < ncT) {
                    load_chunk(region, bml, bn, nc0, pc, pslot);
                } else {
                    int tn = *nextp;
                    if (tn < NT) {
                        int r2, b2, n2, nt2, nc02;
                        geom(tn, r2, b2, n2, nt2, nc02);
                        load_chunk(r2, b2, n2, nc02, pc - ncT, pslot);
                    } else {
                        asm volatile("cp.async.commit_group;" ::: "memory");
                    }
                }
            }
            const uint32_t st = sb + (uint32_t)(gidx % NSTAGE) * STAGE_SB;
#pragma unroll
            for (int ks = 0; ks < 4; ks++) {
                uint32_t ah[4][4], al[4][4], bf[4][2];
                const int arow = wm * 64 + ((lane & 8) ? 8 : 0) + (lane & 7);
                const int acol = ks * 16 + ((lane & 16) ? 8 : 0);
#pragma unroll
                for (int mt = 0; mt < 4; mt++) {
                    uint32_t ad = st + (uint32_t)(arow + mt * 16) * ROWB + acol * 2;
                    ldm_x4(ah[mt], ad);
                    ldm_x4(al[mt], ad + TILE_SB);
                }
                const int brow = ((lane & 16) ? 8 : 0) + (lane & 7);
                const int bcol = ks * 16 + ((lane & 8) ? 8 : 0);
#pragma unroll
                for (int pr = 0; pr < 2; pr++) {
                    uint32_t tmp[4];
                    uint32_t bd = st + 2 * TILE_SB + (uint32_t)(wn * 32 + pr * 16 + brow) * ROWB + bcol * 2;
                    ldm_x4(tmp, bd);
                    bf[2 * pr][0] = tmp[0]; bf[2 * pr][1] = tmp[1];
                    bf[2 * pr + 1][0] = tmp[2]; bf[2 * pr + 1][1] = tmp[3];
                }
#pragma unroll
                for (int mt = 0; mt < 4; mt++)
#pragma unroll
                    for (int nt = 0; nt < 4; nt++)
                        mma_f16(acc[mt][nt], ah[mt], bf[nt]);
#pragma unroll
                for (int mt = 0; mt < 4; mt++)
#pragma unroll
                    for (int nt = 0; nt < 4; nt++)
                        mma_f16(acc[mt][nt], al[mt], bf[nt]);
            }
            gidx++;
        }

        // ---- epilogue ----
        if (do_bn) {
            if (tid < 128) { smS[tid] = 0.f; smQ[tid] = 0.f; }
            __syncthreads();
        }
        const float* bias = region ? bias_r1 : bias_r0;
        const int g = lane >> 2, tg = lane & 3;
        float bnS[4][2], bnQ[4][2];
#pragma unroll
        for (int nt = 0; nt < 4; nt++) { bnS[nt][0] = bnS[nt][1] = 0.f; bnQ[nt][0] = bnQ[nt][1] = 0.f; }

#pragma unroll
        for (int mt = 0; mt < 4; mt++)
#pragma unroll
            for (int h = 0; h < 2; h++) {
                const int gml = bml + wm * 64 + mt * 16 + g + h * 8;
                if (gml >= MREG) continue;
                const int grow = region * MREG + gml;
#pragma unroll
                for (int nt = 0; nt < 4; nt++) {
                    const int gn = bn + wn * 32 + nt * 8 + tg * 2;
                    float v0 = acc[mt][nt][h * 2 + 0];
                    float v1 = acc[mt][nt][h * 2 + 1];
                    if (bias) { v0 += __ldg(bias + gn); v1 += __ldg(bias + gn + 1); }
                    if (Cf) {
                        float2 vv; vv.x = v0; vv.y = v1;
                        *(float2*)(Cf + (size_t)grow * N + gn) = vv;
                    }
                    if (Ch) {
                        __half h0, h1, l0, l1;
                        split_hl(v0, h0, l0); split_hl(v1, h1, l1);
                        *(__half2*)(Ch + (size_t)grow * N + gn) = __halves2half2(h0, h1);
                        *(__half2*)(Cl + (size_t)grow * N + gn) = __halves2half2(l0, l1);
                    }
                    if (do_bn) {
                        bnS[nt][0] += v0; bnQ[nt][0] += v0 * v0;
                        bnS[nt][1] += v1; bnQ[nt][1] += v1 * v1;
                    }
                }
            }

        if (do_bn) {
#pragma unroll
            for (int nt = 0; nt < 4; nt++)
#pragma unroll
                for (int q = 0; q < 2; q++) {
                    float s = bnS[nt][q], qq = bnQ[nt][q];
#pragma unroll
                    for (int off = 4; off < 32; off <<= 1) {
                        s += __shfl_xor_sync(0xffffffffu, s, off);
                        qq += __shfl_xor_sync(0xffffffffu, qq, off);
                    }
                    if (g == 0) {
                        int cl = wn * 32 + nt * 8 + tg * 2 + q;
                        atomicAdd(&smS[cl], s);
                        atomicAdd(&smQ[cl], qq);
                    }
                }
            __syncthreads();
            if (tid < 128) {
                atomicAdd(&g_SUM[bn + tid], smS[tid]);
                atomicAdd(&g_SSQ[bn + tid], smQ[tid]);
            }
        }

        int tn = *nextp;
        if (tn >= NT) break;
        t = tn;
        geom(t, region, bml, bn, ncT, nc0);
    }
    asm volatile("cp.async.wait_group 0;" ::: "memory");
}

// ---------------- BatchNorm finalize + apply ----------------
__global__ void k_bnfinal(const float* __restrict__ gamma, const float* __restrict__ beta) {
    int c = threadIdx.x;
    if (c < HID) {
        float mu = g_SUM[c] * (1.0f / (float)N_TOT);
        float var = g_SSQ[c] * (1.0f / (float)N_TOT) - mu * mu;
        float sc = gamma[c] * rsqrtf(var + EPS);
        g_SCALE[c] = sc;
        g_SHIFT[c] = beta[c] - mu * sc;
    }
}
__global__ void k_bnapply() {
    size_t i = (size_t)blockIdx.x * blockDim.x + threadIdx.x;
    size_t base = i * 8;
    if (base >= (size_t)N_TOT * HID) return;
    int c = (int)(base & (HID - 1));
#pragma unroll
    for (int j = 0; j < 8; j += 2) {
        float2 hf = __half22float2(*(const __half2*)(g_X1H + base + j));
        float2 lf = __half22float2(*(const __half2*)(g_X1L + base + j));
        float x0 = hf.x + lf.x, x1 = hf.y + lf.y;
        float y0 = fmaxf(fmaf(x0, g_SCALE[c + j], g_SHIFT[c + j]), 0.f);
        float y1 = fmaxf(fmaf(x1, g_SCALE[c + j + 1], g_SHIFT[c + j + 1]), 0.f);
        __half h0, h1, l0, l1;
        split_hl(y0, h0, l0); split_hl(y1, h1, l1);
        *(__half2*)(g_AH + base + j) = __halves2half2(h0, h1);
        *(__half2*)(g_AL + base + j) = __halves2half2(l0, l1);
    }
}

// ---------------- launch ----------------
extern "C" void kernel_launch(void* const* d_in, const int* in_sizes, int n_in,
                              void* d_out, int out_size) {
    const float* x_src = (const float*)d_in[0];
    const float* x_dst = (const float*)d_in[1];
    const float* W_src = (const float*)d_in[2];
    const float* b_src = (const float*)d_in[3];
    const float* W_dst = (const float*)d_in[4];
    const float* b_dst = (const float*)d_in[5];
    const float* W1l   = (const float*)d_in[6];
    const float* b1    = (const float*)d_in[7];
    const float* W1r   = (const float*)d_in[8];
    const float* W2l   = (const float*)d_in[9];
    const float* b2    = (const float*)d_in[10];
    const float* W2r   = (const float*)d_in[11];
    const float* gamma = (const float*)d_in[12];
    const float* beta  = (const float*)d_in[13];
    const void*  ei    = (const void*)d_in[14];
    float* out = (float*)d_out;

    static int smem_set = 0;
    if (!smem_set) {
        cudaFuncSetAttribute(k_bgemm, cudaFuncAttributeMaxDynamicSharedMemorySize, GSMEM);
        smem_set = 1;
    }

    __half *AH, *AL, *X1H, *X1L, *MH, *ML, *XSH, *XSL, *XDH, *XDL;
    __half *WS, *WD, *W1L, *W1R, *W2L, *W2R;
    cudaGetSymbolAddress((void**)&AH, g_AH);   cudaGetSymbolAddress((void**)&AL, g_AL);
    cudaGetSymbolAddress((void**)&X1H, g_X1H); cudaGetSymbolAddress((void**)&X1L, g_X1L);
    cudaGetSymbolAddress((void**)&MH, g_MH);   cudaGetSymbolAddress((void**)&ML, g_ML);
    cudaGetSymbolAddress((void**)&XSH, g_XSH); cudaGetSymbolAddress((void**)&XSL, g_XSL);
    cudaGetSymbolAddress((void**)&XDH, g_XDH); cudaGetSymbolAddress((void**)&XDL, g_XDL);
    cudaGetSymbolAddress((void**)&WS, g_WS);   cudaGetSymbolAddress((void**)&WD, g_WD);
    cudaGetSymbolAddress((void**)&W1L, g_W1L); cudaGetSymbolAddress((void**)&W1R, g_W1R);
    cudaGetSymbolAddress((void**)&W2L, g_W2L); cudaGetSymbolAddress((void**)&W2R, g_W2R);

    k_init<<<(N_DST + 255) / 256, 256>>>((const int*)ei);
    k_decode<<<(N_EDGES + 255) / 256, 256>>>(ei);
    ConvTab tb;
    const float* srcs[8] = {W_src, W_dst, W1l, W1r, W2l, W2r, x_src, x_dst};
    __half* hs[8] = {WS, WD, W1L, W1R, W2L, W2R, XSH, XDH};
    __half* ls[8] = {nullptr, nullptr, nullptr, nullptr, nullptr, nullptr, XSL, XDL};
    int ns[8] = {HID * IN_SRC, HID * IN_DST, HID * HID, HID * HID, OUTD * HID, OUTD * HID,
                 N_SRC * IN_SRC, N_DST * IN_DST};
    int cum = 0;
    for (int j = 0; j < 8; j++) {
        tb.s[j] = srcs[j]; tb.h[j] = hs[j]; tb.l[j] = ls[j];
        cum += ns[j] / 4; tb.end[j] = cum;
    }
    k_conv_all<<<(cum + 255) / 256, 256>>>(tb);

    // fused projection GEMM -> AH/AL
    k_bgemm<<<NSM, GTHR, GSMEM>>>(XSH, XSL, WS, IN_SRC,
                                  XDH, XDL, WD, IN_DST,
                                  nullptr, nullptr, nullptr, 0,
                                  b_src, b_dst,
                                  nullptr, AH, AL, HID, 0,
                                  HID / 128, (HID / 128) * 2 * YTILES, 0, 0);

    // CSR build
    k_count<<<(N_EDGES + 255) / 256, 256>>>();
    k_scan<<<1, 1024>>>();
    k_fill<<<(N_EDGES + 255) / 256, 256>>>();

    // layer 1
    k_aggregate<<<N_DST, 128>>>(AH, AL, MH, ML);
    k_bgemm<<<NSM, GTHR, GSMEM>>>(AH, AL, W1R, HID,
                                  AH + (size_t)N_SRC * HID, AL + (size_t)N_SRC * HID, W1R, HID,
                                  MH, ML, W1L, HID,
                                  b1, b1,
                                  nullptr, X1H, X1L, HID, 1,
                                  HID / 128, (HID / 128) * 2 * YTILES, 1, 1);

    // BN finalize + apply (+ReLU)
    k_bnfinal<<<1, 512>>>(gamma, beta);
    k_bnapply<<<(int)(((size_t)N_TOT * HID / 8 + 255) / 256), 256>>>();

    // layer 2
    k_aggregate<<<N_DST, 128>>>(AH, AL, MH, ML);
    k_bgemm<<<NSM, GTHR, GSMEM>>>(AH, AL, W2R, HID,
                                  AH + (size_t)N_SRC * HID, AL + (size_t)N_SRC * HID, W2R, HID,
                                  MH, ML, W2L, HID,
                                  b2, b2,
                                  out, nullptr, nullptr, OUTD, 0,
                                  OUTD / 128, (OUTD / 128) * 2 * YTILES, 1, 2);
}